// round 6
// baseline (speedup 1.0000x reference)
#include <cuda_runtime.h>
#include <cstdint>
#include <math.h>

#define N_TOK 16384
#define D     768
#define DC    64
#define KCODES 8192

// ---------------- scratch (device globals: no runtime allocation) ----------------
__device__ float g_H[N_TOK * D];                 // tanh(Z@W1+b1), 48 MB
__device__ float g_Ze[N_TOK * DC];               // normalized encoder output, 4 MB
__device__ unsigned long long g_best[N_TOK];     // packed (mapped_sim<<32)|(8191-idx)
__device__ float g_loss_part[N_TOK / 16];        // per-block loss partials

// monotonic float->uint mapping (total order preserving)
__device__ __forceinline__ unsigned int fmap(float f) {
    unsigned int u = __float_as_uint(f);
    return (u & 0x80000000u) ? ~u : (u | 0x80000000u);
}

// ---------------- packed f32x2 helpers (Blackwell, sm_100+) ----------------
#define FMA2(acc, a, b) \
    asm("fma.rn.f32x2 %0, %1, %2, %0;" : "+l"(acc) : "l"(a), "l"(b))

__device__ __forceinline__ unsigned long long dup2(float x) {
    unsigned long long r;
    asm("mov.b64 %0, {%1, %1};" : "=l"(r) : "f"(x));
    return r;
}
__device__ __forceinline__ float2 unpk2(unsigned long long v) {
    float2 f;
    asm("mov.b64 {%0, %1}, %2;" : "=f"(f.x), "=f"(f.y) : "l"(v));
    return f;
}

// ---------------- kernel 1: H = tanh(Z @ W1 + b1)  (+ zero loss+codex & g_best) ---
// M=16384, N=768, K=768. BM=BN=128, BK=16, 256 threads, 8x8 per thread.
// Accumulators packed over adjacent n columns (f32x2).
__global__ __launch_bounds__(256, 2) void k_gemm1_tanh(
    const float* __restrict__ A, const float* __restrict__ B,
    const float* __restrict__ bias, float4* __restrict__ zero4)
{
    __shared__ float As[16][132];
    __shared__ float Bs[16][128];
    const int col0 = blockIdx.x * 128;
    const int row0 = blockIdx.y * 128;
    const int tid = threadIdx.x;
    const int tx = tid & 15, ty = tid >> 4;

    // ---- fire-and-forget zeroing of loss + one-hot output + g_best ----
    {
        const unsigned int flat = blockIdx.y * gridDim.x + blockIdx.x;   // 0..767
        const float4 z4 = make_float4(0.f, 0.f, 0.f, 0.f);
        const size_t total4 = ((size_t)N_TOK * KCODES + 1) / 4;
        const size_t stride = (size_t)768 * 256;
        for (size_t i = (size_t)flat * 256 + tid; i < total4; i += stride)
            zero4[i] = z4;
        if (flat == 0 && tid == 0)
            ((float*)zero4)[(size_t)N_TOK * KCODES] = 0.f;
        if (flat < 64) g_best[flat * 256 + tid] = 0ull;
    }

    unsigned long long acc2[8][4];
    #pragma unroll
    for (int i = 0; i < 8; i++)
        #pragma unroll
        for (int p = 0; p < 4; p++) acc2[i][p] = 0ull;

    for (int k0 = 0; k0 < D; k0 += 16) {
        #pragma unroll
        for (int r = 0; r < 2; r++) {             // A tile 128x16 (transposed store)
            int f = tid + r * 256;
            int m = f >> 2;
            int c4 = (f & 3) << 2;
            float4 v = *(const float4*)&A[(size_t)(row0 + m) * D + k0 + c4];
            As[c4 + 0][m] = v.x; As[c4 + 1][m] = v.y;
            As[c4 + 2][m] = v.z; As[c4 + 3][m] = v.w;
        }
        #pragma unroll
        for (int r = 0; r < 2; r++) {             // B tile 16x128
            int f = tid + r * 256;
            int kk = f >> 5;
            int c4 = (f & 31) << 2;
            *(float4*)&Bs[kk][c4] = *(const float4*)&B[(size_t)(k0 + kk) * D + col0 + c4];
        }
        __syncthreads();
        #pragma unroll
        for (int kk = 0; kk < 16; kk++) {
            float a[8];
            *(float4*)&a[0] = *(float4*)&As[kk][ty * 8];
            *(float4*)&a[4] = *(float4*)&As[kk][ty * 8 + 4];
            ulonglong2 b01 = *(const ulonglong2*)&Bs[kk][tx * 8];
            ulonglong2 b23 = *(const ulonglong2*)&Bs[kk][tx * 8 + 4];
            #pragma unroll
            for (int i = 0; i < 8; i++) {
                unsigned long long ad = dup2(a[i]);
                FMA2(acc2[i][0], ad, b01.x);
                FMA2(acc2[i][1], ad, b01.y);
                FMA2(acc2[i][2], ad, b23.x);
                FMA2(acc2[i][3], ad, b23.y);
            }
        }
        __syncthreads();
    }
    #pragma unroll
    for (int i = 0; i < 8; i++) {
        int r = row0 + ty * 8 + i;
        float o[8];
        #pragma unroll
        for (int p = 0; p < 4; p++) {
            float2 u = unpk2(acc2[i][p]);
            o[2 * p] = u.x; o[2 * p + 1] = u.y;
        }
        #pragma unroll
        for (int j = 0; j < 8; j++)
            o[j] = tanhf(o[j] + bias[col0 + tx * 8 + j]);
        *(float4*)&g_H[(size_t)r * D + col0 + tx * 8]     = *(float4*)&o[0];
        *(float4*)&g_H[(size_t)r * D + col0 + tx * 8 + 4] = *(float4*)&o[4];
    }
}

// ---------------- kernel 2: Ze = l2norm(H @ W2 + b2) ----------------
// 32 tokens per block, 256 threads; acc packed over adjacent cols.
__global__ __launch_bounds__(256) void k_gemm2_norm(
    const float* __restrict__ W2, const float* __restrict__ b2)
{
    __shared__ float Hs[32][65];
    __shared__ float Ws[64][64];
    const int tok0 = blockIdx.x * 32;
    const int tid = threadIdx.x;
    const int tl = tid >> 3;
    const int cg = tid & 7;
    unsigned long long acc2[4];
    #pragma unroll
    for (int p = 0; p < 4; p++) acc2[p] = 0ull;

    for (int k0 = 0; k0 < D; k0 += 64) {
        #pragma unroll
        for (int r = 0; r < 4; r++) {
            int f = tid + r * 256;
            int kk = f >> 4, c4 = (f & 15) << 2;
            *(float4*)&Ws[kk][c4] = *(const float4*)&W2[(size_t)(k0 + kk) * DC + c4];
        }
        #pragma unroll
        for (int r = 0; r < 2; r++) {
            int f = tid + r * 256;
            int m = f >> 4, c4 = (f & 15) << 2;
            float4 v = *(const float4*)&g_H[(size_t)(tok0 + m) * D + k0 + c4];
            Hs[m][c4] = v.x; Hs[m][c4 + 1] = v.y; Hs[m][c4 + 2] = v.z; Hs[m][c4 + 3] = v.w;
        }
        __syncthreads();
        #pragma unroll
        for (int kk = 0; kk < 64; kk++) {
            unsigned long long hd = dup2(Hs[tl][kk]);
            ulonglong2 w01 = *(const ulonglong2*)&Ws[kk][cg * 8];
            ulonglong2 w23 = *(const ulonglong2*)&Ws[kk][cg * 8 + 4];
            FMA2(acc2[0], hd, w01.x);
            FMA2(acc2[1], hd, w01.y);
            FMA2(acc2[2], hd, w23.x);
            FMA2(acc2[3], hd, w23.y);
        }
        __syncthreads();
    }
    float acc[8];
    #pragma unroll
    for (int p = 0; p < 4; p++) {
        float2 u = unpk2(acc2[p]);
        acc[2 * p] = u.x; acc[2 * p + 1] = u.y;
    }
    float ss = 0.f;
    #pragma unroll
    for (int j = 0; j < 8; j++) { acc[j] += b2[cg * 8 + j]; ss += acc[j] * acc[j]; }
    ss += __shfl_xor_sync(0xffffffffu, ss, 1);
    ss += __shfl_xor_sync(0xffffffffu, ss, 2);
    ss += __shfl_xor_sync(0xffffffffu, ss, 4);
    float inv = 1.0f / fmaxf(sqrtf(ss), 1e-12f);
    #pragma unroll
    for (int j = 0; j < 8; j++) acc[j] *= inv;
    *(float4*)&g_Ze[(size_t)(tok0 + tl) * DC + cg * 8]     = *(float4*)&acc[0];
    *(float4*)&g_Ze[(size_t)(tok0 + tl) * DC + cg * 8 + 4] = *(float4*)&acc[4];
}

// ---------------- kernel 3: sim = Ze @ emb^T, fused argmax (f32x2, k-packed) ------
// Tile: 64 tokens x 128 codes. 256 threads, each: 4 tokens x 8 codes.
// Accumulators pack even/odd k partial sums; both operands pair for free.
__global__ __launch_bounds__(256, 2) void k_sim_argmax(const float* __restrict__ E)
{
    extern __shared__ float sm[];
    float* zs = sm;                 // [64][68] tokens
    float* es = sm + 64 * 68;       // [128][68] codes
    const int tok0 = blockIdx.y * 64;
    const int c0 = blockIdx.x * 128;
    const int tid = threadIdx.x;
    const int tx = tid & 15, ty = tid >> 4;

    #pragma unroll
    for (int r = 0; r < 4; r++) {                  // zs: 64*16 = 1024 float4s
        int f = tid + 256 * r;
        int m = f >> 4, g = (f & 15) << 2;
        *(float4*)&zs[m * 68 + g] = *(const float4*)&g_Ze[(size_t)(tok0 + m) * DC + g];
    }
    #pragma unroll
    for (int r = 0; r < 8; r++) {                  // es: 128*16 = 2048 float4s
        int f = tid + 256 * r;
        int m = f >> 4, g = (f & 15) << 2;
        *(float4*)&es[m * 68 + g] = *(const float4*)&E[(size_t)(c0 + m) * DC + g];
    }
    __syncthreads();

    unsigned long long acc2[4][8];
    #pragma unroll
    for (int i = 0; i < 4; i++)
        #pragma unroll
        for (int j = 0; j < 8; j++) acc2[i][j] = 0ull;

    #pragma unroll 4
    for (int k4 = 0; k4 < 16; k4++) {
        ulonglong2 a2[4];
        #pragma unroll
        for (int i = 0; i < 4; i++)
            a2[i] = *(const ulonglong2*)&zs[(ty * 4 + i) * 68 + k4 * 4];
        #pragma unroll
        for (int j = 0; j < 8; j++) {
            ulonglong2 b = *(const ulonglong2*)&es[(tx + 16 * j) * 68 + k4 * 4];
            #pragma unroll
            for (int i = 0; i < 4; i++) {
                FMA2(acc2[i][j], a2[i].x, b.x);
                FMA2(acc2[i][j], a2[i].y, b.y);
            }
        }
    }

    #pragma unroll
    for (int i = 0; i < 4; i++) {
        float2 u0 = unpk2(acc2[i][0]);
        float bv = u0.x + u0.y;
        int bc = c0 + tx;
        #pragma unroll
        for (int j = 1; j < 8; j++) {              // codes ascending -> ties keep lowest
            float2 u = unpk2(acc2[i][j]);
            float v = u.x + u.y;
            int c = c0 + tx + 16 * j;
            if (v > bv) { bv = v; bc = c; }
        }
        unsigned long long p =
            ((unsigned long long)fmap(bv) << 32) | (unsigned int)(KCODES - 1 - bc);
        #pragma unroll
        for (int s = 1; s < 16; s <<= 1) {
            unsigned long long q = __shfl_xor_sync(0xffffffffu, p, s);
            if (q > p) p = q;
        }
        if (tx == 0) atomicMax(&g_best[tok0 + ty * 4 + i], p);
    }
}

// ---------------- kernel 4: scatter one-hot ----------------
__global__ void k_scatter(float* __restrict__ codex)
{
    int t = blockIdx.x * 256 + threadIdx.x;
    if (t < N_TOK) {
        int c = KCODES - 1 - (int)(g_best[t] & 0xffffffffu);
        codex[(size_t)t * KCODES + c] = 1.0f;
    }
}

// ---------------- kernel 5: gather + loss partials + LayerNorm + out = y @ Wp + bp ----
// 16 tokens per block, 128 threads; acc packed over adjacent tokens.
__global__ __launch_bounds__(128) void k_ln_gemm3(
    const float* __restrict__ E, const float* __restrict__ gamma,
    const float* __restrict__ beta, const float* __restrict__ Wp,
    const float* __restrict__ bp, float* __restrict__ out)
{
    __shared__ float ys[64][16];
    __shared__ float sds[16];
    const int tok0 = blockIdx.x * 16;
    const int tid = threadIdx.x;
    const int tl = tid >> 3, cg = tid & 7;
    const int t = tok0 + tl;

    int code = KCODES - 1 - (int)(g_best[t] & 0xffffffffu);
    float q[8], z[8];
    *(float4*)&q[0] = *(const float4*)&E[(size_t)code * DC + cg * 8];
    *(float4*)&q[4] = *(const float4*)&E[(size_t)code * DC + cg * 8 + 4];
    *(float4*)&z[0] = *(const float4*)&g_Ze[(size_t)t * DC + cg * 8];
    *(float4*)&z[4] = *(const float4*)&g_Ze[(size_t)t * DC + cg * 8 + 4];

    float s = 0.f, s2 = 0.f, sd = 0.f;
    #pragma unroll
    for (int e = 0; e < 8; e++) {
        s += q[e]; s2 += q[e] * q[e];
        float d = q[e] - z[e]; sd += d * d;
    }
    #pragma unroll
    for (int w = 1; w < 8; w <<= 1) {
        s  += __shfl_xor_sync(0xffffffffu, s,  w);
        s2 += __shfl_xor_sync(0xffffffffu, s2, w);
        sd += __shfl_xor_sync(0xffffffffu, sd, w);
    }
    float mean = s * (1.0f / 64.0f);
    float var  = s2 * (1.0f / 64.0f) - mean * mean;
    float rstd = rsqrtf(var + 1e-5f);
    #pragma unroll
    for (int e = 0; e < 8; e++) {
        int c = cg * 8 + e;
        ys[c][tl] = (q[e] - mean) * rstd * gamma[c] + beta[c];
    }
    if (cg == 0) sds[tl] = sd;
    __syncthreads();
    if (tid == 0) {
        float tot = 0.f;
        #pragma unroll
        for (int i = 0; i < 16; i++) tot += sds[i];
        g_loss_part[blockIdx.x] = tot;
    }

    for (int n = tid; n < D; n += 128) {
        unsigned long long acc2[8];
        #pragma unroll
        for (int p = 0; p < 8; p++) acc2[p] = 0ull;
        #pragma unroll 8
        for (int c = 0; c < DC; c++) {
            unsigned long long wd = dup2(Wp[(size_t)c * D + n]);
            ulonglong2 y01 = *(const ulonglong2*)&ys[c][0];
            ulonglong2 y23 = *(const ulonglong2*)&ys[c][4];
            ulonglong2 y45 = *(const ulonglong2*)&ys[c][8];
            ulonglong2 y67 = *(const ulonglong2*)&ys[c][12];
            FMA2(acc2[0], wd, y01.x); FMA2(acc2[1], wd, y01.y);
            FMA2(acc2[2], wd, y23.x); FMA2(acc2[3], wd, y23.y);
            FMA2(acc2[4], wd, y45.x); FMA2(acc2[5], wd, y45.y);
            FMA2(acc2[6], wd, y67.x); FMA2(acc2[7], wd, y67.y);
        }
        float bb = bp[n];
        #pragma unroll
        for (int p = 0; p < 8; p++) {
            float2 u = unpk2(acc2[p]);
            out[(size_t)(tok0 + 2 * p) * D + n]     = u.x + bb;
            out[(size_t)(tok0 + 2 * p + 1) * D + n] = u.y + bb;
        }
    }
}

// ---------------- kernel 6: deterministic loss reduction ----------------
__global__ void k_loss_reduce(float* __restrict__ loss_out)
{
    __shared__ float red[256];
    int tid = threadIdx.x;
    float s = 0.f;
    for (int i = tid; i < N_TOK / 16; i += 256) s += g_loss_part[i];
    red[tid] = s;
    __syncthreads();
    for (int w = 128; w > 0; w >>= 1) {
        if (tid < w) red[tid] += red[tid + w];
        __syncthreads();
    }
    if (tid == 0) loss_out[0] = red[0] * (1.0f / (float)(N_TOK * DC));
}

// ---------------- launch ----------------
extern "C" void kernel_launch(void* const* d_in, const int* in_sizes, int n_in,
                              void* d_out, int out_size)
{
    const float* Z   = (const float*)d_in[0];
    const float* W1  = (const float*)d_in[1];
    const float* b1  = (const float*)d_in[2];
    const float* W2  = (const float*)d_in[3];
    const float* b2  = (const float*)d_in[4];
    const float* emb = (const float*)d_in[5];
    const float* gam = (const float*)d_in[6];
    const float* bet = (const float*)d_in[7];
    const float* Wp  = (const float*)d_in[8];
    const float* bp  = (const float*)d_in[9];

    float* out   = (float*)d_out;
    float* lossp = out + (size_t)N_TOK * D;         // scalar after out (16B-aligned)
    float* codex = lossp + 1;                        // one-hot after loss

    (void)in_sizes; (void)n_in; (void)out_size;

    const int SIM_SMEM = (64 + 128) * 68 * 4;        // 52224 B
    cudaFuncSetAttribute(k_sim_argmax,
                         cudaFuncAttributeMaxDynamicSharedMemorySize, SIM_SMEM);

    k_gemm1_tanh<<<dim3(D / 128, N_TOK / 128), 256>>>(Z, W1, b1, (float4*)lossp);
    k_gemm2_norm<<<N_TOK / 32, 256>>>(W2, b2);
    k_sim_argmax<<<dim3(KCODES / 128, N_TOK / 64), 256, SIM_SMEM>>>(emb);
    k_scatter<<<(N_TOK + 255) / 256, 256>>>(codex);
    k_ln_gemm3<<<N_TOK / 16, 128>>>(emb, gam, bet, Wp, bp, out);
    k_loss_reduce<<<1, 256>>>(lossp);
}

// round 7
// speedup vs baseline: 1.0022x; 1.0022x over previous
#include <cuda_runtime.h>
#include <cstdint>
#include <math.h>

#define N_TOK 16384
#define D     768
#define DC    64
#define KCODES 8192

// ---------------- scratch (device globals: no runtime allocation) ----------------
__device__ float g_H[N_TOK * D];                 // tanh(Z@W1+b1), 48 MB
__device__ float g_Ze[N_TOK * DC];               // normalized encoder output, 4 MB
__device__ unsigned long long g_best[N_TOK];     // packed (mapped_sim<<32)|(8191-idx)
__device__ float g_loss_part[N_TOK / 16];        // per-block loss partials

// monotonic float->uint mapping (total order preserving)
__device__ __forceinline__ unsigned int fmap(float f) {
    unsigned int u = __float_as_uint(f);
    return (u & 0x80000000u) ? ~u : (u | 0x80000000u);
}

// ---------------- packed f32x2 helpers (Blackwell, sm_100+) ----------------
#define FMA2(acc, a, b) \
    asm("fma.rn.f32x2 %0, %1, %2, %0;" : "+l"(acc) : "l"(a), "l"(b))

__device__ __forceinline__ unsigned long long dup2(float x) {
    unsigned long long r;
    asm("mov.b64 %0, {%1, %1};" : "=l"(r) : "f"(x));
    return r;
}
__device__ __forceinline__ float2 unpk2(unsigned long long v) {
    float2 f;
    asm("mov.b64 {%0, %1}, %2;" : "=f"(f.x), "=f"(f.y) : "l"(v));
    return f;
}

// ---------------- kernel 1: H = tanh(Z @ W1 + b1)  (+ zero loss+codex & g_best) ---
// M=16384, N=768, K=768. BM=BN=128, BK=16, 256 threads, 8x8 per thread.
// Accumulators packed over adjacent n columns (f32x2).
__global__ __launch_bounds__(256, 2) void k_gemm1_tanh(
    const float* __restrict__ A, const float* __restrict__ B,
    const float* __restrict__ bias, float4* __restrict__ zero4)
{
    __shared__ float As[16][132];
    __shared__ float Bs[16][128];
    const int col0 = blockIdx.x * 128;
    const int row0 = blockIdx.y * 128;
    const int tid = threadIdx.x;
    const int tx = tid & 15, ty = tid >> 4;

    // ---- fire-and-forget zeroing of loss + one-hot output + g_best ----
    {
        const unsigned int flat = blockIdx.y * gridDim.x + blockIdx.x;   // 0..767
        const float4 z4 = make_float4(0.f, 0.f, 0.f, 0.f);
        const size_t total4 = ((size_t)N_TOK * KCODES + 1) / 4;
        const size_t stride = (size_t)768 * 256;
        for (size_t i = (size_t)flat * 256 + tid; i < total4; i += stride)
            zero4[i] = z4;
        if (flat == 0 && tid == 0)
            ((float*)zero4)[(size_t)N_TOK * KCODES] = 0.f;
        if (flat < 64) g_best[flat * 256 + tid] = 0ull;
    }

    unsigned long long acc2[8][4];
    #pragma unroll
    for (int i = 0; i < 8; i++)
        #pragma unroll
        for (int p = 0; p < 4; p++) acc2[i][p] = 0ull;

    for (int k0 = 0; k0 < D; k0 += 16) {
        #pragma unroll
        for (int r = 0; r < 2; r++) {             // A tile 128x16 (transposed store)
            int f = tid + r * 256;
            int m = f >> 2;
            int c4 = (f & 3) << 2;
            float4 v = *(const float4*)&A[(size_t)(row0 + m) * D + k0 + c4];
            As[c4 + 0][m] = v.x; As[c4 + 1][m] = v.y;
            As[c4 + 2][m] = v.z; As[c4 + 3][m] = v.w;
        }
        #pragma unroll
        for (int r = 0; r < 2; r++) {             // B tile 16x128
            int f = tid + r * 256;
            int kk = f >> 5;
            int c4 = (f & 31) << 2;
            *(float4*)&Bs[kk][c4] = *(const float4*)&B[(size_t)(k0 + kk) * D + col0 + c4];
        }
        __syncthreads();
        #pragma unroll
        for (int kk = 0; kk < 16; kk++) {
            float a[8];
            *(float4*)&a[0] = *(float4*)&As[kk][ty * 8];
            *(float4*)&a[4] = *(float4*)&As[kk][ty * 8 + 4];
            ulonglong2 b01 = *(const ulonglong2*)&Bs[kk][tx * 8];
            ulonglong2 b23 = *(const ulonglong2*)&Bs[kk][tx * 8 + 4];
            #pragma unroll
            for (int i = 0; i < 8; i++) {
                unsigned long long ad = dup2(a[i]);
                FMA2(acc2[i][0], ad, b01.x);
                FMA2(acc2[i][1], ad, b01.y);
                FMA2(acc2[i][2], ad, b23.x);
                FMA2(acc2[i][3], ad, b23.y);
            }
        }
        __syncthreads();
    }
    #pragma unroll
    for (int i = 0; i < 8; i++) {
        int r = row0 + ty * 8 + i;
        float o[8];
        #pragma unroll
        for (int p = 0; p < 4; p++) {
            float2 u = unpk2(acc2[i][p]);
            o[2 * p] = u.x; o[2 * p + 1] = u.y;
        }
        #pragma unroll
        for (int j = 0; j < 8; j++)
            o[j] = tanhf(o[j] + bias[col0 + tx * 8 + j]);
        *(float4*)&g_H[(size_t)r * D + col0 + tx * 8]     = *(float4*)&o[0];
        *(float4*)&g_H[(size_t)r * D + col0 + tx * 8 + 4] = *(float4*)&o[4];
    }
}

// ---------------- kernel 2: Ze = l2norm(H @ W2 + b2) ----------------
// 32 tokens per block, 256 threads; acc packed over adjacent cols.
__global__ __launch_bounds__(256) void k_gemm2_norm(
    const float* __restrict__ W2, const float* __restrict__ b2)
{
    __shared__ float Hs[32][65];
    __shared__ float Ws[64][64];
    const int tok0 = blockIdx.x * 32;
    const int tid = threadIdx.x;
    const int tl = tid >> 3;
    const int cg = tid & 7;
    unsigned long long acc2[4];
    #pragma unroll
    for (int p = 0; p < 4; p++) acc2[p] = 0ull;

    for (int k0 = 0; k0 < D; k0 += 64) {
        #pragma unroll
        for (int r = 0; r < 4; r++) {
            int f = tid + r * 256;
            int kk = f >> 4, c4 = (f & 15) << 2;
            *(float4*)&Ws[kk][c4] = *(const float4*)&W2[(size_t)(k0 + kk) * DC + c4];
        }
        #pragma unroll
        for (int r = 0; r < 2; r++) {
            int f = tid + r * 256;
            int m = f >> 4, c4 = (f & 15) << 2;
            float4 v = *(const float4*)&g_H[(size_t)(tok0 + m) * D + k0 + c4];
            Hs[m][c4] = v.x; Hs[m][c4 + 1] = v.y; Hs[m][c4 + 2] = v.z; Hs[m][c4 + 3] = v.w;
        }
        __syncthreads();
        #pragma unroll
        for (int kk = 0; kk < 64; kk++) {
            unsigned long long hd = dup2(Hs[tl][kk]);
            ulonglong2 w01 = *(const ulonglong2*)&Ws[kk][cg * 8];
            ulonglong2 w23 = *(const ulonglong2*)&Ws[kk][cg * 8 + 4];
            FMA2(acc2[0], hd, w01.x);
            FMA2(acc2[1], hd, w01.y);
            FMA2(acc2[2], hd, w23.x);
            FMA2(acc2[3], hd, w23.y);
        }
        __syncthreads();
    }
    float acc[8];
    #pragma unroll
    for (int p = 0; p < 4; p++) {
        float2 u = unpk2(acc2[p]);
        acc[2 * p] = u.x; acc[2 * p + 1] = u.y;
    }
    float ss = 0.f;
    #pragma unroll
    for (int j = 0; j < 8; j++) { acc[j] += b2[cg * 8 + j]; ss += acc[j] * acc[j]; }
    ss += __shfl_xor_sync(0xffffffffu, ss, 1);
    ss += __shfl_xor_sync(0xffffffffu, ss, 2);
    ss += __shfl_xor_sync(0xffffffffu, ss, 4);
    float inv = 1.0f / fmaxf(sqrtf(ss), 1e-12f);
    #pragma unroll
    for (int j = 0; j < 8; j++) acc[j] *= inv;
    *(float4*)&g_Ze[(size_t)(tok0 + tl) * DC + cg * 8]     = *(float4*)&acc[0];
    *(float4*)&g_Ze[(size_t)(tok0 + tl) * DC + cg * 8 + 4] = *(float4*)&acc[4];
}

// ---------------- kernel 3: sim = Ze @ emb^T, fused argmax (f32x2, k-packed) ------
// Tile: 64 tokens x 128 codes. 256 threads, each: 4 tokens x 8 codes.
// Accumulators pack even/odd k partial sums; both operands pair for free.
__global__ __launch_bounds__(256, 2) void k_sim_argmax(const float* __restrict__ E)
{
    extern __shared__ float sm[];
    float* zs = sm;                 // [64][68] tokens
    float* es = sm + 64 * 68;       // [128][68] codes
    const int tok0 = blockIdx.y * 64;
    const int c0 = blockIdx.x * 128;
    const int tid = threadIdx.x;
    const int tx = tid & 15, ty = tid >> 4;

    #pragma unroll
    for (int r = 0; r < 4; r++) {                  // zs: 64*16 = 1024 float4s
        int f = tid + 256 * r;
        int m = f >> 4, g = (f & 15) << 2;
        *(float4*)&zs[m * 68 + g] = *(const float4*)&g_Ze[(size_t)(tok0 + m) * DC + g];
    }
    #pragma unroll
    for (int r = 0; r < 8; r++) {                  // es: 128*16 = 2048 float4s
        int f = tid + 256 * r;
        int m = f >> 4, g = (f & 15) << 2;
        *(float4*)&es[m * 68 + g] = *(const float4*)&E[(size_t)(c0 + m) * DC + g];
    }
    __syncthreads();

    unsigned long long acc2[4][8];
    #pragma unroll
    for (int i = 0; i < 4; i++)
        #pragma unroll
        for (int j = 0; j < 8; j++) acc2[i][j] = 0ull;

    #pragma unroll 4
    for (int k4 = 0; k4 < 16; k4++) {
        ulonglong2 a2[4];
        #pragma unroll
        for (int i = 0; i < 4; i++)
            a2[i] = *(const ulonglong2*)&zs[(ty * 4 + i) * 68 + k4 * 4];
        #pragma unroll
        for (int j = 0; j < 8; j++) {
            ulonglong2 b = *(const ulonglong2*)&es[(tx + 16 * j) * 68 + k4 * 4];
            #pragma unroll
            for (int i = 0; i < 4; i++) {
                FMA2(acc2[i][j], a2[i].x, b.x);
                FMA2(acc2[i][j], a2[i].y, b.y);
            }
        }
    }

    #pragma unroll
    for (int i = 0; i < 4; i++) {
        float2 u0 = unpk2(acc2[i][0]);
        float bv = u0.x + u0.y;
        int bc = c0 + tx;
        #pragma unroll
        for (int j = 1; j < 8; j++) {              // codes ascending -> ties keep lowest
            float2 u = unpk2(acc2[i][j]);
            float v = u.x + u.y;
            int c = c0 + tx + 16 * j;
            if (v > bv) { bv = v; bc = c; }
        }
        unsigned long long p =
            ((unsigned long long)fmap(bv) << 32) | (unsigned int)(KCODES - 1 - bc);
        #pragma unroll
        for (int s = 1; s < 16; s <<= 1) {
            unsigned long long q = __shfl_xor_sync(0xffffffffu, p, s);
            if (q > p) p = q;
        }
        if (tx == 0) atomicMax(&g_best[tok0 + ty * 4 + i], p);
    }
}

// ---------------- kernel 4: scatter one-hot ----------------
__global__ void k_scatter(float* __restrict__ codex)
{
    int t = blockIdx.x * 256 + threadIdx.x;
    if (t < N_TOK) {
        int c = KCODES - 1 - (int)(g_best[t] & 0xffffffffu);
        codex[(size_t)t * KCODES + c] = 1.0f;
    }
}

// ---------------- kernel 5: gather + loss partials + LayerNorm + out = y @ Wp + bp ----
// 16 tokens per block, 128 threads; acc packed over adjacent tokens.
__global__ __launch_bounds__(128) void k_ln_gemm3(
    const float* __restrict__ E, const float* __restrict__ gamma,
    const float* __restrict__ beta, const float* __restrict__ Wp,
    const float* __restrict__ bp, float* __restrict__ out)
{
    __shared__ float ys[64][16];
    __shared__ float sds[16];
    const int tok0 = blockIdx.x * 16;
    const int tid = threadIdx.x;
    const int tl = tid >> 3, cg = tid & 7;
    const int t = tok0 + tl;

    int code = KCODES - 1 - (int)(g_best[t] & 0xffffffffu);
    float q[8], z[8];
    *(float4*)&q[0] = *(const float4*)&E[(size_t)code * DC + cg * 8];
    *(float4*)&q[4] = *(const float4*)&E[(size_t)code * DC + cg * 8 + 4];
    *(float4*)&z[0] = *(const float4*)&g_Ze[(size_t)t * DC + cg * 8];
    *(float4*)&z[4] = *(const float4*)&g_Ze[(size_t)t * DC + cg * 8 + 4];

    float s = 0.f, s2 = 0.f, sd = 0.f;
    #pragma unroll
    for (int e = 0; e < 8; e++) {
        s += q[e]; s2 += q[e] * q[e];
        float d = q[e] - z[e]; sd += d * d;
    }
    #pragma unroll
    for (int w = 1; w < 8; w <<= 1) {
        s  += __shfl_xor_sync(0xffffffffu, s,  w);
        s2 += __shfl_xor_sync(0xffffffffu, s2, w);
        sd += __shfl_xor_sync(0xffffffffu, sd, w);
    }
    float mean = s * (1.0f / 64.0f);
    float var  = s2 * (1.0f / 64.0f) - mean * mean;
    float rstd = rsqrtf(var + 1e-5f);
    #pragma unroll
    for (int e = 0; e < 8; e++) {
        int c = cg * 8 + e;
        ys[c][tl] = (q[e] - mean) * rstd * gamma[c] + beta[c];
    }
    if (cg == 0) sds[tl] = sd;
    __syncthreads();
    if (tid == 0) {
        float tot = 0.f;
        #pragma unroll
        for (int i = 0; i < 16; i++) tot += sds[i];
        g_loss_part[blockIdx.x] = tot;
    }

    for (int n = tid; n < D; n += 128) {
        unsigned long long acc2[8];
        #pragma unroll
        for (int p = 0; p < 8; p++) acc2[p] = 0ull;
        #pragma unroll 8
        for (int c = 0; c < DC; c++) {
            unsigned long long wd = dup2(Wp[(size_t)c * D + n]);
            ulonglong2 y01 = *(const ulonglong2*)&ys[c][0];
            ulonglong2 y23 = *(const ulonglong2*)&ys[c][4];
            ulonglong2 y45 = *(const ulonglong2*)&ys[c][8];
            ulonglong2 y67 = *(const ulonglong2*)&ys[c][12];
            FMA2(acc2[0], wd, y01.x); FMA2(acc2[1], wd, y01.y);
            FMA2(acc2[2], wd, y23.x); FMA2(acc2[3], wd, y23.y);
            FMA2(acc2[4], wd, y45.x); FMA2(acc2[5], wd, y45.y);
            FMA2(acc2[6], wd, y67.x); FMA2(acc2[7], wd, y67.y);
        }
        float bb = bp[n];
        #pragma unroll
        for (int p = 0; p < 8; p++) {
            float2 u = unpk2(acc2[p]);
            out[(size_t)(tok0 + 2 * p) * D + n]     = u.x + bb;
            out[(size_t)(tok0 + 2 * p + 1) * D + n] = u.y + bb;
        }
    }
}

// ---------------- kernel 6: deterministic loss reduction ----------------
__global__ void k_loss_reduce(float* __restrict__ loss_out)
{
    __shared__ float red[256];
    int tid = threadIdx.x;
    float s = 0.f;
    for (int i = tid; i < N_TOK / 16; i += 256) s += g_loss_part[i];
    red[tid] = s;
    __syncthreads();
    for (int w = 128; w > 0; w >>= 1) {
        if (tid < w) red[tid] += red[tid + w];
        __syncthreads();
    }
    if (tid == 0) loss_out[0] = red[0] * (1.0f / (float)(N_TOK * DC));
}

// ---------------- launch ----------------
extern "C" void kernel_launch(void* const* d_in, const int* in_sizes, int n_in,
                              void* d_out, int out_size)
{
    const float* Z   = (const float*)d_in[0];
    const float* W1  = (const float*)d_in[1];
    const float* b1  = (const float*)d_in[2];
    const float* W2  = (const float*)d_in[3];
    const float* b2  = (const float*)d_in[4];
    const float* emb = (const float*)d_in[5];
    const float* gam = (const float*)d_in[6];
    const float* bet = (const float*)d_in[7];
    const float* Wp  = (const float*)d_in[8];
    const float* bp  = (const float*)d_in[9];

    float* out   = (float*)d_out;
    float* lossp = out + (size_t)N_TOK * D;         // scalar after out (16B-aligned)
    float* codex = lossp + 1;                        // one-hot after loss

    (void)in_sizes; (void)n_in; (void)out_size;

    const int SIM_SMEM = (64 + 128) * 68 * 4;        // 52224 B
    cudaFuncSetAttribute(k_sim_argmax,
                         cudaFuncAttributeMaxDynamicSharedMemorySize, SIM_SMEM);

    k_gemm1_tanh<<<dim3(D / 128, N_TOK / 128), 256>>>(Z, W1, b1, (float4*)lossp);
    k_gemm2_norm<<<N_TOK / 32, 256>>>(W2, b2);
    k_sim_argmax<<<dim3(KCODES / 128, N_TOK / 64), 256, SIM_SMEM>>>(emb);
    k_scatter<<<(N_TOK + 255) / 256, 256>>>(codex);
    k_ln_gemm3<<<N_TOK / 16, 128>>>(emb, gam, bet, Wp, bp, out);
    k_loss_reduce<<<1, 256>>>(lossp);
}